// round 5
// baseline (speedup 1.0000x reference)
#include <cuda_runtime.h>
#include <cstdint>
#include <cstddef>

#define MAXN 10000
#define MAXE 160000
#define NSM  148

typedef unsigned long long ull;

__device__ float g_x0[MAXN * 16];
__device__ float g_x1[MAXN * 12];
__device__ float g_qd0[MAXN * 8];
__device__ float g_qd1[MAXN * 6];
__device__ float g_logit[MAXE];
__device__ float g_v[MAXE * 28];       // SoA: [j*E + e]
__device__ float g_m[MAXN];
__device__ float g_z[MAXN];
__device__ float g_agg[MAXN * 28];     // AoS
__device__ float g_h2k[(size_t)MAXE * 64];   // K-MLP hidden2, AoS rows
__device__ float g_h2v[(size_t)MAXE * 64];   // V-MLP hidden2, AoS rows

__device__ __forceinline__ float frelu(float x) { return x > 0.f ? x : 0.f; }

// ---- packed f32x2 helpers (Blackwell FFMA2) -------------------------------
__device__ __forceinline__ ull pack2(float lo, float hi) {
    ull r; asm("mov.b64 %0, {%1, %2};" : "=l"(r) : "f"(lo), "f"(hi)); return r;
}
__device__ __forceinline__ void unpack2(ull v, float& lo, float& hi) {
    asm("mov.b64 {%0, %1}, %2;" : "=f"(lo), "=f"(hi) : "l"(v));
}
__device__ __forceinline__ void ffma2(ull& d, ull a, ull b) {
    asm("fma.rn.f32x2 %0, %1, %2, %0;" : "+l"(d) : "l"(a), "l"(b));
}

// dot of (4*NU2) floats, 4 packed accumulators (chain depth NU2/2)
template <int NU2>
__device__ __forceinline__ float dotp(const float* __restrict__ w,
                                      const ull* __restrict__ h) {
    ull a0 = 0ull, a1 = 0ull, a2 = 0ull, a3 = 0ull;
    const ulonglong2* wp = reinterpret_cast<const ulonglong2*>(w);
#pragma unroll
    for (int t = 0; t < NU2; t += 2) {
        ulonglong2 w0 = wp[t];
        ulonglong2 w1 = wp[t + 1];
        ffma2(a0, w0.x, h[2 * t + 0]);
        ffma2(a1, w0.y, h[2 * t + 1]);
        ffma2(a2, w1.x, h[2 * t + 2]);
        ffma2(a3, w1.y, h[2 * t + 3]);
    }
    float l0, h0, l1, h1, l2, h2, l3, h3;
    unpack2(a0, l0, h0); unpack2(a1, l1, h1);
    unpack2(a2, l2, h2); unpack2(a3, l3, h3);
    return ((l0 + h0) + (l1 + h1)) + ((l2 + h2) + (l3 + h3));
}

__device__ __forceinline__ void atomicMaxF(float* addr, float v) {
    if (v >= 0.f) atomicMax((int*)addr, __float_as_int(v));
    else          atomicMin((unsigned int*)addr, __float_as_uint(v));
}

// ---------------------------------------------------------------------------
// Kernel A: node prep (x = ir_linear(node_attr); qd = (q @ Wd) precontracted)
// ---------------------------------------------------------------------------
__global__ void node_prep_kernel(const float* __restrict__ na,
                                 const float* __restrict__ Win0,
                                 const float* __restrict__ Win1,
                                 const float* __restrict__ Wq0,
                                 const float* __restrict__ Wq1,
                                 const float* __restrict__ Wd0,
                                 const float* __restrict__ Wd1,
                                 int N) {
    __shared__ float sWin0[512], sWin1[32], sWq0[128], sWq1[8], sWd0[64], sWd1[4];
    int tid = threadIdx.x;
    for (int i = tid; i < 512; i += blockDim.x) sWin0[i] = Win0[i];
    for (int i = tid; i < 32;  i += blockDim.x) sWin1[i] = Win1[i];
    for (int i = tid; i < 128; i += blockDim.x) sWq0[i]  = Wq0[i];
    for (int i = tid; i < 8;   i += blockDim.x) sWq1[i]  = Wq1[i];
    for (int i = tid; i < 64;  i += blockDim.x) sWd0[i]  = Wd0[i];
    for (int i = tid; i < 4;   i += blockDim.x) sWd1[i]  = Wd1[i];
    __syncthreads();

    int n = blockIdx.x * blockDim.x + tid;
    if (n >= N) return;

    const float* p = na + (size_t)n * 56;
    float a0[32], a1[24];
#pragma unroll
    for (int i = 0; i < 32; i++) a0[i] = p[i];
#pragma unroll
    for (int i = 0; i < 24; i++) a1[i] = p[32 + i];

    float x0[16];
#pragma unroll
    for (int o = 0; o < 16; o++) {
        float s = 0.f;
#pragma unroll
        for (int i = 0; i < 32; i++) s = fmaf(a0[i], sWin0[i * 16 + o], s);
        x0[o] = s * 0.17677669529663687f;   // 1/sqrt(32)
    }
    float x1[12];
#pragma unroll
    for (int o = 0; o < 4; o++)
#pragma unroll
        for (int c = 0; c < 3; c++) {
            float s = 0.f;
#pragma unroll
            for (int m = 0; m < 8; m++) s = fmaf(a1[m * 3 + c], sWin1[m * 4 + o], s);
            x1[o * 3 + c] = s * 0.35355339059327373f;  // 1/sqrt(8)
        }

    float q0[8];
#pragma unroll
    for (int b = 0; b < 8; b++) {
        float s = 0.f;
#pragma unroll
        for (int o = 0; o < 16; o++) s = fmaf(x0[o], sWq0[o * 8 + b], s);
        q0[b] = s * 0.25f;                   // 1/sqrt(16)
    }
    float q1[6];
#pragma unroll
    for (int j = 0; j < 2; j++)
#pragma unroll
        for (int c = 0; c < 3; c++) {
            float s = 0.f;
#pragma unroll
            for (int o = 0; o < 4; o++) s = fmaf(x1[o * 3 + c], sWq1[o * 2 + j], s);
            q1[j * 3 + c] = s * 0.5f;        // 1/sqrt(4)
        }

#pragma unroll
    for (int j = 0; j < 8; j++) {
        float s = 0.f;
#pragma unroll
        for (int i = 0; i < 8; i++) s = fmaf(q0[i], sWd0[i * 8 + j], s);
        g_qd0[(size_t)n * 8 + j] = s;
    }
#pragma unroll
    for (int j = 0; j < 2; j++)
#pragma unroll
        for (int c = 0; c < 3; c++) {
            float s = 0.f;
#pragma unroll
            for (int i = 0; i < 2; i++) s = fmaf(q1[i * 3 + c], sWd1[i * 2 + j], s);
            g_qd1[(size_t)n * 6 + j * 3 + c] = s;
        }

#pragma unroll
    for (int o = 0; o < 16; o++) g_x0[(size_t)n * 16 + o] = x0[o];
#pragma unroll
    for (int o = 0; o < 12; o++) g_x1[(size_t)n * 12 + o] = x1[o];
}

// ---------------------------------------------------------------------------
__global__ void init_kernel(int N) {
    int i = blockIdx.x * blockDim.x + threadIdx.x;
    if (i < N * 28) g_agg[i] = 0.f;
    if (i < N) {
        g_m[i] = __int_as_float(0xff800000);  // -inf
        g_z[i] = 0.f;
    }
}

// ---------------------------------------------------------------------------
// FRONT kernel: both MLP fronts (32->64->64), writes h2K / h2V
// smem: [W1K^T 2048][b1K 64][W2K^T 4096][b2K 64][W1V^T ...][...] = 12544 fl
// ---------------------------------------------------------------------------
#define F_OW1K 0
#define F_OB1K 2048
#define F_OW2K 2112
#define F_OB2K 6208
#define F_OW1V 6272
#define F_OB1V 8320
#define F_OW2V 8384
#define F_OB2V 12480
#define F_FLOATS 12544

__device__ __forceinline__ void front_one(const float* __restrict__ sm,
                                          int oW1, int oB1, int oW2, int oB2,
                                          const ull* __restrict__ eap,
                                          float* __restrict__ g_h2, size_t e) {
    ull h1p[32];
#pragma unroll 4
    for (int o = 0; o < 64; o += 2) {
        float lo = frelu(sm[oB1 + o]     + dotp<8>(sm + oW1 + o * 32,       eap));
        float hi = frelu(sm[oB1 + o + 1] + dotp<8>(sm + oW1 + (o + 1) * 32, eap));
        h1p[o >> 1] = pack2(lo, hi);
    }
    ull buf0 = 0ull, buf1;
#pragma unroll 4
    for (int o = 0; o < 64; o += 2) {
        float lo = frelu(sm[oB2 + o]     + dotp<16>(sm + oW2 + o * 64,       h1p));
        float hi = frelu(sm[oB2 + o + 1] + dotp<16>(sm + oW2 + (o + 1) * 64, h1p));
        if ((o & 2) == 0) {
            buf0 = pack2(lo, hi);
        } else {
            buf1 = pack2(lo, hi);
            ulonglong2 st; st.x = buf0; st.y = buf1;
            reinterpret_cast<ulonglong2*>(g_h2 + e * 64)[o >> 2] = st;
        }
    }
}

__global__ void __launch_bounds__(128, 4)
front_kernel(const float* __restrict__ edge_attr,
             const float* __restrict__ fcW1, const float* __restrict__ fcb1,
             const float* __restrict__ fcW2, const float* __restrict__ fcb2,
             const float* __restrict__ fkW1, const float* __restrict__ fkb1,
             const float* __restrict__ fkW2, const float* __restrict__ fkb2,
             int E) {
    extern __shared__ float sm[];
    int tid = threadIdx.x, bs = blockDim.x;
    for (int i = tid; i < 2048; i += bs) { int o = i >> 5, c = i & 31; sm[F_OW1K + i] = fkW1[c * 64 + o]; }
    for (int i = tid; i < 64;   i += bs) sm[F_OB1K + i] = fkb1[i];
    for (int i = tid; i < 4096; i += bs) { int o = i >> 6, c = i & 63; sm[F_OW2K + i] = fkW2[c * 64 + o]; }
    for (int i = tid; i < 64;   i += bs) sm[F_OB2K + i] = fkb2[i];
    for (int i = tid; i < 2048; i += bs) { int o = i >> 5, c = i & 31; sm[F_OW1V + i] = fcW1[c * 64 + o]; }
    for (int i = tid; i < 64;   i += bs) sm[F_OB1V + i] = fcb1[i];
    for (int i = tid; i < 4096; i += bs) { int o = i >> 6, c = i & 63; sm[F_OW2V + i] = fcW2[c * 64 + o]; }
    for (int i = tid; i < 64;   i += bs) sm[F_OB2V + i] = fcb2[i];
    __syncthreads();

    for (int e = blockIdx.x * bs + tid; e < E; e += gridDim.x * bs) {
        ull eap[16];
        const ulonglong2* ea2 = reinterpret_cast<const ulonglong2*>(edge_attr + (size_t)e * 32);
#pragma unroll
        for (int t = 0; t < 8; t++) {
            ulonglong2 v = ea2[t];
            eap[2 * t] = v.x; eap[2 * t + 1] = v.y;
        }
        front_one(sm, F_OW1K, F_OB1K, F_OW2K, F_OB2K, eap, g_h2k, (size_t)e);
        front_one(sm, F_OW1V, F_OB1V, F_OW2V, F_OB2V, eap, g_h2v, (size_t)e);
    }
}

// ---------------------------------------------------------------------------
// L3K kernel: K layer-3 + TP contraction + logit + atomicMax
// smem: W3K^T (200 rows x 64) + bias 200 = 13000 floats
// ---------------------------------------------------------------------------
__global__ void __launch_bounds__(128, 4)
l3k_kernel(const float* __restrict__ edge_sh,
           const int*   __restrict__ eidx,
           const float* __restrict__ fkW3, const float* __restrict__ fkb3,
           int E) {
    extern __shared__ float sm[];
    int tid = threadIdx.x, bs = blockDim.x;
    for (int i = tid; i < 12800; i += bs) { int w = i >> 6, c = i & 63; sm[i] = fkW3[c * 200 + w]; }
    for (int i = tid; i < 200;   i += bs) sm[12800 + i] = fkb3[i];
    __syncthreads();
    const float* B3 = sm + 12800;

    const float NORM = 0.22360679774997896f;  // 1/sqrt(20)
    const float I3   = 0.5773502691896258f;   // 1/sqrt(3)

    for (int e = blockIdx.x * bs + tid; e < E; e += gridDim.x * bs) {
        int s = eidx[e];
        int d = eidx[E + e];
        float4 shv = reinterpret_cast<const float4*>(edge_sh)[e];
        float sh0 = shv.x, shx = shv.y, shy = shv.z, shz = shv.w;

        ull h2p[32];
        const ulonglong2* h2r = reinterpret_cast<const ulonglong2*>(g_h2k + (size_t)e * 64);
#pragma unroll
        for (int t = 0; t < 16; t++) {
            ulonglong2 v = h2r[t];
            h2p[2 * t] = v.x; h2p[2 * t + 1] = v.y;
        }

        float xl0[16], xl1[12], ul1[4];
#pragma unroll
        for (int o = 0; o < 16; o++) xl0[o] = g_x0[(size_t)s * 16 + o];
#pragma unroll
        for (int o = 0; o < 12; o++) xl1[o] = g_x1[(size_t)s * 12 + o];
#pragma unroll
        for (int j = 0; j < 4; j++)
            ul1[j] = xl1[j * 3] * shx + xl1[j * 3 + 1] * shy + xl1[j * 3 + 2] * shz;

        float logit = 0.f;
#pragma unroll 1
        for (int b = 0; b < 8; b++) {
            float acc0 = 0.f;
#pragma unroll 2
            for (int a = 0; a < 16; a++) {
                int wi = a * 8 + b;
                float w = dotp<16>(sm + wi * 64, h2p) + B3[wi];
                acc0 = fmaf(xl0[a], w, acc0);
            }
            float acc1 = 0.f;
#pragma unroll 2
            for (int a = 0; a < 4; a++) {
                int wi = 168 + a * 8 + b;
                float w = dotp<16>(sm + wi * 64, h2p) + B3[wi];
                acc1 = fmaf(ul1[a], w, acc1);
            }
            float k0b = NORM * fmaf(sh0, acc0, I3 * acc1);
            logit = fmaf(g_qd0[(size_t)d * 8 + b], k0b, logit);
        }
#pragma unroll 1
        for (int j = 0; j < 2; j++) {
            float c01 = 0.f;
#pragma unroll 2
            for (int a = 0; a < 16; a++) {
                int wi = 128 + a * 2 + j;
                float w = dotp<16>(sm + wi * 64, h2p) + B3[wi];
                c01 = fmaf(xl0[a], w, c01);
            }
            float dx = 0.f, dy = 0.f, dz = 0.f;
#pragma unroll 2
            for (int a = 0; a < 4; a++) {
                int wi = 160 + a * 2 + j;
                float w = dotp<16>(sm + wi * 64, h2p) + B3[wi];
                dx = fmaf(xl1[a * 3 + 0], w, dx);
                dy = fmaf(xl1[a * 3 + 1], w, dy);
                dz = fmaf(xl1[a * 3 + 2], w, dz);
            }
            float k1x = NORM * (shx * c01 + sh0 * dx);
            float k1y = NORM * (shy * c01 + sh0 * dy);
            float k1z = NORM * (shz * c01 + sh0 * dz);
            logit += I3 * (g_qd1[(size_t)d * 6 + j * 3 + 0] * k1x +
                           g_qd1[(size_t)d * 6 + j * 3 + 1] * k1y +
                           g_qd1[(size_t)d * 6 + j * 3 + 2] * k1z);
        }
        logit *= 0.31622776601683794f;  // 1/sqrt(10)
        g_logit[e] = logit;
        atomicMaxF(&g_m[d], logit);
    }
}

// ---------------------------------------------------------------------------
// L3V kernel (HALF = 0/1): V layer-3 + TP contraction for half the outputs
// smem rows (200 x 64) + bias 200 = 13000 floats
//   r <128 : w00 a=r>>3 b=r&7  -> wi = a*16 + HALF*8 + b
//   r <160 : w01 t=r-128 a=t>>1 j=t&1 -> wi = 256 + a*4 + HALF*2 + j
//   r <168 : w10 t=r-160 a=t>>1 j=t&1 -> wi = 320 + a*4 + HALF*2 + j
//   r <200 : w11 t=r-168 a=t>>3 b=t&7 -> wi = 336 + a*16 + HALF*8 + b
// ---------------------------------------------------------------------------
template <int HALF>
__device__ __forceinline__ int v_wi(int r) {
    if (r < 128) { int a = r >> 3, b = r & 7;          return a * 16 + HALF * 8 + b; }
    if (r < 160) { int t = r - 128; int a = t >> 1;     return 256 + a * 4 + HALF * 2 + (t & 1); }
    if (r < 168) { int t = r - 160; int a = t >> 1;     return 320 + a * 4 + HALF * 2 + (t & 1); }
    { int t = r - 168; int a = t >> 3, b = t & 7;       return 336 + a * 16 + HALF * 8 + b; }
}

template <int HALF>
__global__ void __launch_bounds__(128, 4)
l3v_kernel(const float* __restrict__ edge_sh,
           const int*   __restrict__ eidx,
           const float* __restrict__ fcW3, const float* __restrict__ fcb3,
           int E) {
    extern __shared__ float sm[];
    int tid = threadIdx.x, bs = blockDim.x;
    for (int i = tid; i < 12800; i += bs) {
        int r = i >> 6, c = i & 63;
        sm[i] = fcW3[c * 400 + v_wi<HALF>(r)];
    }
    for (int i = tid; i < 200; i += bs) sm[12800 + i] = fcb3[v_wi<HALF>(i)];
    __syncthreads();
    const float* B3 = sm + 12800;

    const float NORM = 0.22360679774997896f;  // 1/sqrt(20)
    const float I3   = 0.5773502691896258f;   // 1/sqrt(3)

    for (int e = blockIdx.x * bs + tid; e < E; e += gridDim.x * bs) {
        int s = eidx[e];
        float4 shv = reinterpret_cast<const float4*>(edge_sh)[e];
        float sh0 = shv.x, shx = shv.y, shy = shv.z, shz = shv.w;

        ull h2p[32];
        const ulonglong2* h2r = reinterpret_cast<const ulonglong2*>(g_h2v + (size_t)e * 64);
#pragma unroll
        for (int t = 0; t < 16; t++) {
            ulonglong2 v = h2r[t];
            h2p[2 * t] = v.x; h2p[2 * t + 1] = v.y;
        }

        float xl0[16], xl1[12], ul1[4];
#pragma unroll
        for (int o = 0; o < 16; o++) xl0[o] = g_x0[(size_t)s * 16 + o];
#pragma unroll
        for (int o = 0; o < 12; o++) xl1[o] = g_x1[(size_t)s * 12 + o];
#pragma unroll
        for (int j = 0; j < 4; j++)
            ul1[j] = xl1[j * 3] * shx + xl1[j * 3 + 1] * shy + xl1[j * 3 + 2] * shz;

#pragma unroll 1
        for (int b = 0; b < 8; b++) {
            float acc0 = 0.f;
#pragma unroll 2
            for (int a = 0; a < 16; a++) {
                int r = a * 8 + b;
                float w = dotp<16>(sm + r * 64, h2p) + B3[r];
                acc0 = fmaf(xl0[a], w, acc0);
            }
            float acc1 = 0.f;
#pragma unroll 2
            for (int a = 0; a < 4; a++) {
                int r = 168 + a * 8 + b;
                float w = dotp<16>(sm + r * 64, h2p) + B3[r];
                acc1 = fmaf(ul1[a], w, acc1);
            }
            int bg = HALF * 8 + b;
            g_v[(size_t)bg * E + e] = NORM * fmaf(sh0, acc0, I3 * acc1);
        }
#pragma unroll 1
        for (int j = 0; j < 2; j++) {
            float c01 = 0.f;
#pragma unroll 2
            for (int a = 0; a < 16; a++) {
                int r = 128 + a * 2 + j;
                float w = dotp<16>(sm + r * 64, h2p) + B3[r];
                c01 = fmaf(xl0[a], w, c01);
            }
            float dx = 0.f, dy = 0.f, dz = 0.f;
#pragma unroll 2
            for (int a = 0; a < 4; a++) {
                int r = 160 + a * 2 + j;
                float w = dotp<16>(sm + r * 64, h2p) + B3[r];
                dx = fmaf(xl1[a * 3 + 0], w, dx);
                dy = fmaf(xl1[a * 3 + 1], w, dy);
                dz = fmaf(xl1[a * 3 + 2], w, dz);
            }
            int jg = HALF * 2 + j;
            g_v[(size_t)(16 + jg * 3 + 0) * E + e] = NORM * (shx * c01 + sh0 * dx);
            g_v[(size_t)(16 + jg * 3 + 1) * E + e] = NORM * (shy * c01 + sh0 * dy);
            g_v[(size_t)(16 + jg * 3 + 2) * E + e] = NORM * (shz * c01 + sh0 * dz);
        }
    }
}

// ---------------------------------------------------------------------------
__global__ void softmax_agg_kernel(const int* __restrict__ eidx, int E) {
    int e = blockIdx.x * blockDim.x + threadIdx.x;
    if (e >= E) return;
    int d = eidx[E + e];
    float p = __expf(g_logit[e] - g_m[d]);
    atomicAdd(&g_z[d], p);
#pragma unroll
    for (int j = 0; j < 28; j++)
        atomicAdd(&g_agg[(size_t)d * 28 + j], p * g_v[(size_t)j * E + e]);
}

// ---------------------------------------------------------------------------
__global__ void node_out_kernel(const float* __restrict__ na,
                                const float* __restrict__ Wo0,
                                const float* __restrict__ Wo1,
                                float* __restrict__ out, int N) {
    __shared__ float sW0[512], sW1[32];
    int tid = threadIdx.x;
    for (int i = tid; i < 512; i += blockDim.x) sW0[i] = Wo0[i];
    for (int i = tid; i < 32;  i += blockDim.x) sW1[i] = Wo1[i];
    __syncthreads();

    int n = blockIdx.x * blockDim.x + tid;
    if (n >= N) return;
    float z = g_z[n];
    float zi = z > 0.f ? 1.f / z : 0.f;
    float ag[28];
#pragma unroll
    for (int j = 0; j < 28; j++) ag[j] = g_agg[(size_t)n * 28 + j] * zi;

#pragma unroll
    for (int o = 0; o < 32; o++) {
        float s = 0.f;
#pragma unroll
        for (int a = 0; a < 16; a++) s = fmaf(ag[a], sW0[a * 32 + o], s);
        out[(size_t)n * 56 + o] = fmaf(s, 0.25f, na[(size_t)n * 56 + o]);
    }
#pragma unroll
    for (int o = 0; o < 8; o++)
#pragma unroll
        for (int c = 0; c < 3; c++) {
            float s = 0.f;
#pragma unroll
            for (int a = 0; a < 4; a++) s = fmaf(ag[16 + a * 3 + c], sW1[a * 8 + o], s);
            out[(size_t)n * 56 + 32 + o * 3 + c] =
                fmaf(s, 0.5f, na[(size_t)n * 56 + 32 + o * 3 + c]);
        }
}

// ---------------------------------------------------------------------------
extern "C" void kernel_launch(void* const* d_in, const int* in_sizes, int n_in,
                              void* d_out, int out_size) {
    const float* node_attr  = (const float*)d_in[0];
    const float* edge_attr  = (const float*)d_in[1];
    const float* edge_sh    = (const float*)d_in[2];
    const int*   edge_index = (const int*)  d_in[3];
    const float* W_in0  = (const float*)d_in[4];
    const float* W_in1  = (const float*)d_in[5];
    const float* Wq0    = (const float*)d_in[6];
    const float* Wq1    = (const float*)d_in[7];
    const float* Wd0    = (const float*)d_in[8];
    const float* Wd1    = (const float*)d_in[9];
    const float* W_out0 = (const float*)d_in[10];
    const float* W_out1 = (const float*)d_in[11];
    const float* fcW1 = (const float*)d_in[12];
    const float* fcb1 = (const float*)d_in[13];
    const float* fcW2 = (const float*)d_in[14];
    const float* fcb2 = (const float*)d_in[15];
    const float* fcW3 = (const float*)d_in[16];
    const float* fcb3 = (const float*)d_in[17];
    const float* fkW1 = (const float*)d_in[18];
    const float* fkb1 = (const float*)d_in[19];
    const float* fkW2 = (const float*)d_in[20];
    const float* fkb2 = (const float*)d_in[21];
    const float* fkW3 = (const float*)d_in[22];
    const float* fkb3 = (const float*)d_in[23];
    float* out = (float*)d_out;

    int N = in_sizes[0] / 56;
    int E = in_sizes[2] / 4;

    const int FRONT_SMEM = F_FLOATS * (int)sizeof(float);   // 50176 B
    const int L3_SMEM    = 13000 * (int)sizeof(float);      // 52000 B

    cudaFuncSetAttribute(front_kernel,
                         cudaFuncAttributeMaxDynamicSharedMemorySize, FRONT_SMEM);
    cudaFuncSetAttribute(l3k_kernel,
                         cudaFuncAttributeMaxDynamicSharedMemorySize, L3_SMEM);
    cudaFuncSetAttribute(l3v_kernel<0>,
                         cudaFuncAttributeMaxDynamicSharedMemorySize, L3_SMEM);
    cudaFuncSetAttribute(l3v_kernel<1>,
                         cudaFuncAttributeMaxDynamicSharedMemorySize, L3_SMEM);

    node_prep_kernel<<<(N + 127) / 128, 128>>>(node_attr, W_in0, W_in1, Wq0, Wq1,
                                               Wd0, Wd1, N);
    init_kernel<<<(N * 28 + 255) / 256, 256>>>(N);
    front_kernel<<<NSM * 4, 128, FRONT_SMEM>>>(edge_attr,
                                               fcW1, fcb1, fcW2, fcb2,
                                               fkW1, fkb1, fkW2, fkb2, E);
    l3k_kernel<<<NSM * 4, 128, L3_SMEM>>>(edge_sh, edge_index, fkW3, fkb3, E);
    l3v_kernel<0><<<NSM * 4, 128, L3_SMEM>>>(edge_sh, edge_index, fcW3, fcb3, E);
    l3v_kernel<1><<<NSM * 4, 128, L3_SMEM>>>(edge_sh, edge_index, fcW3, fcb3, E);
    softmax_agg_kernel<<<(E + 255) / 256, 256>>>(edge_index, E);
    node_out_kernel<<<(N + 127) / 128, 128>>>(node_attr, W_out0, W_out1, out, N);
}

// round 6
// speedup vs baseline: 1.2090x; 1.2090x over previous
#include <cuda_runtime.h>
#include <cstdint>
#include <cstddef>

#define MAXN 10000
#define MAXE 160000
#define NSM  148

typedef unsigned long long ull;

__device__ float g_x0[MAXN * 16];
__device__ float g_x1[MAXN * 12];
__device__ float g_qd0[MAXN * 8];
__device__ float g_qd1[MAXN * 6];
__device__ float g_logit[MAXE];
__device__ float g_v[MAXE * 28];       // SoA: [j*E + e]
__device__ float g_m[MAXN];
__device__ float g_z[MAXN];
__device__ float g_agg[MAXN * 28];     // AoS
__device__ float g_h2k[(size_t)MAXE * 64];
__device__ float g_h2v[(size_t)MAXE * 64];

__device__ __forceinline__ float frelu(float x) { return x > 0.f ? x : 0.f; }

// ---- packed f32x2 helpers (Blackwell FFMA2) -------------------------------
__device__ __forceinline__ ull pack2(float lo, float hi) {
    ull r; asm("mov.b64 %0, {%1, %2};" : "=l"(r) : "f"(lo), "f"(hi)); return r;
}
__device__ __forceinline__ void unpack2(ull v, float& lo, float& hi) {
    asm("mov.b64 {%0, %1}, %2;" : "=f"(lo), "=f"(hi) : "l"(v));
}
__device__ __forceinline__ void ffma2(ull& d, ull a, ull b) {
    asm("fma.rn.f32x2 %0, %1, %2, %0;" : "+l"(d) : "l"(a), "l"(b));
}

// dual-edge dot of (4*NU2) floats: ONE weight fetch feeds BOTH edges
template <int NU2>
__device__ __forceinline__ void dotp2(const float* __restrict__ w,
                                      const ull* __restrict__ hA,
                                      const ull* __restrict__ hB,
                                      float& rA, float& rB) {
    ull a0 = 0ull, a1 = 0ull, b0 = 0ull, b1 = 0ull;
    const ulonglong2* wp = reinterpret_cast<const ulonglong2*>(w);
#pragma unroll
    for (int t = 0; t < NU2; t++) {
        ulonglong2 ww = wp[t];
        ffma2(a0, ww.x, hA[2 * t]);
        ffma2(a1, ww.y, hA[2 * t + 1]);
        ffma2(b0, ww.x, hB[2 * t]);
        ffma2(b1, ww.y, hB[2 * t + 1]);
    }
    float x0, x1, x2, x3;
    unpack2(a0, x0, x1); unpack2(a1, x2, x3);
    rA = (x0 + x1) + (x2 + x3);
    unpack2(b0, x0, x1); unpack2(b1, x2, x3);
    rB = (x0 + x1) + (x2 + x3);
}

__device__ __forceinline__ void atomicMaxF(float* addr, float v) {
    if (v >= 0.f) atomicMax((int*)addr, __float_as_int(v));
    else          atomicMin((unsigned int*)addr, __float_as_uint(v));
}

// ---------------------------------------------------------------------------
// Kernel A: node prep (x = ir_linear(node_attr); qd = (q @ Wd) precontracted)
// ---------------------------------------------------------------------------
__global__ void node_prep_kernel(const float* __restrict__ na,
                                 const float* __restrict__ Win0,
                                 const float* __restrict__ Win1,
                                 const float* __restrict__ Wq0,
                                 const float* __restrict__ Wq1,
                                 const float* __restrict__ Wd0,
                                 const float* __restrict__ Wd1,
                                 int N) {
    __shared__ float sWin0[512], sWin1[32], sWq0[128], sWq1[8], sWd0[64], sWd1[4];
    int tid = threadIdx.x;
    for (int i = tid; i < 512; i += blockDim.x) sWin0[i] = Win0[i];
    for (int i = tid; i < 32;  i += blockDim.x) sWin1[i] = Win1[i];
    for (int i = tid; i < 128; i += blockDim.x) sWq0[i]  = Wq0[i];
    for (int i = tid; i < 8;   i += blockDim.x) sWq1[i]  = Wq1[i];
    for (int i = tid; i < 64;  i += blockDim.x) sWd0[i]  = Wd0[i];
    for (int i = tid; i < 4;   i += blockDim.x) sWd1[i]  = Wd1[i];
    __syncthreads();

    int n = blockIdx.x * blockDim.x + tid;
    if (n >= N) return;

    const float* p = na + (size_t)n * 56;
    float a0[32], a1[24];
#pragma unroll
    for (int i = 0; i < 32; i++) a0[i] = p[i];
#pragma unroll
    for (int i = 0; i < 24; i++) a1[i] = p[32 + i];

    float x0[16];
#pragma unroll
    for (int o = 0; o < 16; o++) {
        float s = 0.f;
#pragma unroll
        for (int i = 0; i < 32; i++) s = fmaf(a0[i], sWin0[i * 16 + o], s);
        x0[o] = s * 0.17677669529663687f;   // 1/sqrt(32)
    }
    float x1[12];
#pragma unroll
    for (int o = 0; o < 4; o++)
#pragma unroll
        for (int c = 0; c < 3; c++) {
            float s = 0.f;
#pragma unroll
            for (int m = 0; m < 8; m++) s = fmaf(a1[m * 3 + c], sWin1[m * 4 + o], s);
            x1[o * 3 + c] = s * 0.35355339059327373f;  // 1/sqrt(8)
        }

    float q0[8];
#pragma unroll
    for (int b = 0; b < 8; b++) {
        float s = 0.f;
#pragma unroll
        for (int o = 0; o < 16; o++) s = fmaf(x0[o], sWq0[o * 8 + b], s);
        q0[b] = s * 0.25f;                   // 1/sqrt(16)
    }
    float q1[6];
#pragma unroll
    for (int j = 0; j < 2; j++)
#pragma unroll
        for (int c = 0; c < 3; c++) {
            float s = 0.f;
#pragma unroll
            for (int o = 0; o < 4; o++) s = fmaf(x1[o * 3 + c], sWq1[o * 2 + j], s);
            q1[j * 3 + c] = s * 0.5f;        // 1/sqrt(4)
        }

#pragma unroll
    for (int j = 0; j < 8; j++) {
        float s = 0.f;
#pragma unroll
        for (int i = 0; i < 8; i++) s = fmaf(q0[i], sWd0[i * 8 + j], s);
        g_qd0[(size_t)n * 8 + j] = s;
    }
#pragma unroll
    for (int j = 0; j < 2; j++)
#pragma unroll
        for (int c = 0; c < 3; c++) {
            float s = 0.f;
#pragma unroll
            for (int i = 0; i < 2; i++) s = fmaf(q1[i * 3 + c], sWd1[i * 2 + j], s);
            g_qd1[(size_t)n * 6 + j * 3 + c] = s;
        }

#pragma unroll
    for (int o = 0; o < 16; o++) g_x0[(size_t)n * 16 + o] = x0[o];
#pragma unroll
    for (int o = 0; o < 12; o++) g_x1[(size_t)n * 12 + o] = x1[o];
}

// ---------------------------------------------------------------------------
__global__ void init_kernel(int N) {
    int i = blockIdx.x * blockDim.x + threadIdx.x;
    if (i < N * 28) g_agg[i] = 0.f;
    if (i < N) {
        g_m[i] = __int_as_float(0xff800000);  // -inf
        g_z[i] = 0.f;
    }
}

// ---------------------------------------------------------------------------
// FRONT kernel (EPT=2): both MLP fronts (32->64->64), writes h2K / h2V
// ---------------------------------------------------------------------------
#define F_OW1K 0
#define F_OB1K 2048
#define F_OW2K 2112
#define F_OB2K 6208
#define F_OW1V 6272
#define F_OB1V 8320
#define F_OW2V 8384
#define F_OB2V 12480
#define F_FLOATS 12544

__device__ __forceinline__ void front_one2(const float* __restrict__ sm,
                                           int oW1, int oB1, int oW2, int oB2,
                                           const float* __restrict__ edge_attr,
                                           float* __restrict__ gh2,
                                           size_t e0, size_t e1, bool hb) {
    ull eapA[16], eapB[16];
    {
        const ulonglong2* a2 = reinterpret_cast<const ulonglong2*>(edge_attr + e0 * 32);
        const ulonglong2* b2 = reinterpret_cast<const ulonglong2*>(edge_attr + e1 * 32);
#pragma unroll
        for (int t = 0; t < 8; t++) {
            ulonglong2 va = a2[t]; ulonglong2 vb = b2[t];
            eapA[2 * t] = va.x; eapA[2 * t + 1] = va.y;
            eapB[2 * t] = vb.x; eapB[2 * t + 1] = vb.y;
        }
    }
    ull h1A[32], h1B[32];
#pragma unroll 4
    for (int o = 0; o < 64; o += 2) {
        float loA, loB, hiA, hiB;
        dotp2<8>(sm + oW1 + o * 32,       eapA, eapB, loA, loB);
        dotp2<8>(sm + oW1 + (o + 1) * 32, eapA, eapB, hiA, hiB);
        float b_lo = sm[oB1 + o], b_hi = sm[oB1 + o + 1];
        h1A[o >> 1] = pack2(frelu(b_lo + loA), frelu(b_hi + hiA));
        h1B[o >> 1] = pack2(frelu(b_lo + loB), frelu(b_hi + hiB));
    }
#pragma unroll 2
    for (int o = 0; o < 64; o += 4) {
        float vA[4], vB[4];
#pragma unroll
        for (int k = 0; k < 4; k++) {
            float a, b;
            dotp2<16>(sm + oW2 + (o + k) * 64, h1A, h1B, a, b);
            float bias = sm[oB2 + o + k];
            vA[k] = frelu(bias + a);
            vB[k] = frelu(bias + b);
        }
        ulonglong2 sA; sA.x = pack2(vA[0], vA[1]); sA.y = pack2(vA[2], vA[3]);
        reinterpret_cast<ulonglong2*>(gh2 + e0 * 64)[o >> 2] = sA;
        if (hb) {
            ulonglong2 sB; sB.x = pack2(vB[0], vB[1]); sB.y = pack2(vB[2], vB[3]);
            reinterpret_cast<ulonglong2*>(gh2 + e1 * 64)[o >> 2] = sB;
        }
    }
}

__global__ void __launch_bounds__(128, 2)
front_kernel(const float* __restrict__ edge_attr,
             const float* __restrict__ fcW1, const float* __restrict__ fcb1,
             const float* __restrict__ fcW2, const float* __restrict__ fcb2,
             const float* __restrict__ fkW1, const float* __restrict__ fkb1,
             const float* __restrict__ fkW2, const float* __restrict__ fkb2,
             int E) {
    extern __shared__ float sm[];
    int tid = threadIdx.x, bs = blockDim.x;
    for (int i = tid; i < 2048; i += bs) { int o = i >> 5, c = i & 31; sm[F_OW1K + i] = fkW1[c * 64 + o]; }
    for (int i = tid; i < 64;   i += bs) sm[F_OB1K + i] = fkb1[i];
    for (int i = tid; i < 4096; i += bs) { int o = i >> 6, c = i & 63; sm[F_OW2K + i] = fkW2[c * 64 + o]; }
    for (int i = tid; i < 64;   i += bs) sm[F_OB2K + i] = fkb2[i];
    for (int i = tid; i < 2048; i += bs) { int o = i >> 5, c = i & 31; sm[F_OW1V + i] = fcW1[c * 64 + o]; }
    for (int i = tid; i < 64;   i += bs) sm[F_OB1V + i] = fcb1[i];
    for (int i = tid; i < 4096; i += bs) { int o = i >> 6, c = i & 63; sm[F_OW2V + i] = fcW2[c * 64 + o]; }
    for (int i = tid; i < 64;   i += bs) sm[F_OB2V + i] = fcb2[i];
    __syncthreads();

    int stride = gridDim.x * bs;
    for (int e0 = blockIdx.x * bs + tid; e0 < E; e0 += 2 * stride) {
        int e1 = e0 + stride;
        bool hb = e1 < E;
        size_t e1c = hb ? (size_t)e1 : (size_t)e0;
        front_one2(sm, F_OW1K, F_OB1K, F_OW2K, F_OB2K, edge_attr, g_h2k,
                   (size_t)e0, e1c, hb);
        front_one2(sm, F_OW1V, F_OB1V, F_OW2V, F_OB2V, edge_attr, g_h2v,
                   (size_t)e0, e1c, hb);
    }
}

// ---------------------------------------------------------------------------
// L3K kernel (EPT=2): K layer-3 + TP contraction + logit + atomicMax
// smem: W3K^T (200 x 64) + bias 200
// ---------------------------------------------------------------------------
__global__ void __launch_bounds__(128, 2)
l3k_kernel(const float* __restrict__ edge_sh,
           const int*   __restrict__ eidx,
           const float* __restrict__ fkW3, const float* __restrict__ fkb3,
           int E) {
    extern __shared__ float sm[];
    int tid = threadIdx.x, bs = blockDim.x;
    for (int i = tid; i < 12800; i += bs) { int w = i >> 6, c = i & 63; sm[i] = fkW3[c * 200 + w]; }
    for (int i = tid; i < 200;   i += bs) sm[12800 + i] = fkb3[i];
    __syncthreads();
    const float* B3 = sm + 12800;

    const float NORM = 0.22360679774997896f;  // 1/sqrt(20)
    const float I3   = 0.5773502691896258f;   // 1/sqrt(3)

    int stride = gridDim.x * bs;
    for (int e0 = blockIdx.x * bs + tid; e0 < E; e0 += 2 * stride) {
        int e1 = e0 + stride;
        bool hb = e1 < E;
        size_t e1c = hb ? (size_t)e1 : (size_t)e0;

        int sA = eidx[e0],        dA = eidx[E + e0];
        int sB = eidx[e1c],       dB = eidx[E + e1c];
        float4 shA = reinterpret_cast<const float4*>(edge_sh)[e0];
        float4 shB = reinterpret_cast<const float4*>(edge_sh)[e1c];

        ull h2A[32], h2B[32];
        {
            const ulonglong2* ra = reinterpret_cast<const ulonglong2*>(g_h2k + (size_t)e0 * 64);
            const ulonglong2* rb = reinterpret_cast<const ulonglong2*>(g_h2k + e1c * 64);
#pragma unroll
            for (int t = 0; t < 16; t++) {
                ulonglong2 va = ra[t]; ulonglong2 vb = rb[t];
                h2A[2 * t] = va.x; h2A[2 * t + 1] = va.y;
                h2B[2 * t] = vb.x; h2B[2 * t + 1] = vb.y;
            }
        }

        float xl0A[16], xl0B[16], xl1A[12], xl1B[12], ul1A[4], ul1B[4];
#pragma unroll
        for (int o = 0; o < 16; o++) {
            xl0A[o] = g_x0[(size_t)sA * 16 + o];
            xl0B[o] = g_x0[(size_t)sB * 16 + o];
        }
#pragma unroll
        for (int o = 0; o < 12; o++) {
            xl1A[o] = g_x1[(size_t)sA * 12 + o];
            xl1B[o] = g_x1[(size_t)sB * 12 + o];
        }
#pragma unroll
        for (int j = 0; j < 4; j++) {
            ul1A[j] = xl1A[j * 3] * shA.y + xl1A[j * 3 + 1] * shA.z + xl1A[j * 3 + 2] * shA.w;
            ul1B[j] = xl1B[j * 3] * shB.y + xl1B[j * 3 + 1] * shB.z + xl1B[j * 3 + 2] * shB.w;
        }

        float logitA = 0.f, logitB = 0.f;
#pragma unroll 1
        for (int b = 0; b < 8; b++) {
            float a0A = 0.f, a0B = 0.f;
#pragma unroll 2
            for (int a = 0; a < 16; a++) {
                int wi = a * 8 + b;
                float wA, wB;
                dotp2<16>(sm + wi * 64, h2A, h2B, wA, wB);
                float bb = B3[wi];
                a0A = fmaf(xl0A[a], wA + bb, a0A);
                a0B = fmaf(xl0B[a], wB + bb, a0B);
            }
            float a1A = 0.f, a1B = 0.f;
#pragma unroll 2
            for (int a = 0; a < 4; a++) {
                int wi = 168 + a * 8 + b;
                float wA, wB;
                dotp2<16>(sm + wi * 64, h2A, h2B, wA, wB);
                float bb = B3[wi];
                a1A = fmaf(ul1A[a], wA + bb, a1A);
                a1B = fmaf(ul1B[a], wB + bb, a1B);
            }
            float k0A = NORM * fmaf(shA.x, a0A, I3 * a1A);
            float k0B = NORM * fmaf(shB.x, a0B, I3 * a1B);
            logitA = fmaf(g_qd0[(size_t)dA * 8 + b], k0A, logitA);
            logitB = fmaf(g_qd0[(size_t)dB * 8 + b], k0B, logitB);
        }
#pragma unroll 1
        for (int j = 0; j < 2; j++) {
            float cA = 0.f, cB = 0.f;
#pragma unroll 2
            for (int a = 0; a < 16; a++) {
                int wi = 128 + a * 2 + j;
                float wA, wB;
                dotp2<16>(sm + wi * 64, h2A, h2B, wA, wB);
                float bb = B3[wi];
                cA = fmaf(xl0A[a], wA + bb, cA);
                cB = fmaf(xl0B[a], wB + bb, cB);
            }
            float dxA = 0.f, dyA = 0.f, dzA = 0.f;
            float dxB = 0.f, dyB = 0.f, dzB = 0.f;
#pragma unroll 2
            for (int a = 0; a < 4; a++) {
                int wi = 160 + a * 2 + j;
                float wA, wB;
                dotp2<16>(sm + wi * 64, h2A, h2B, wA, wB);
                float bb = B3[wi];
                wA += bb; wB += bb;
                dxA = fmaf(xl1A[a * 3 + 0], wA, dxA);
                dyA = fmaf(xl1A[a * 3 + 1], wA, dyA);
                dzA = fmaf(xl1A[a * 3 + 2], wA, dzA);
                dxB = fmaf(xl1B[a * 3 + 0], wB, dxB);
                dyB = fmaf(xl1B[a * 3 + 1], wB, dyB);
                dzB = fmaf(xl1B[a * 3 + 2], wB, dzB);
            }
            float k1xA = NORM * (shA.y * cA + shA.x * dxA);
            float k1yA = NORM * (shA.z * cA + shA.x * dyA);
            float k1zA = NORM * (shA.w * cA + shA.x * dzA);
            float k1xB = NORM * (shB.y * cB + shB.x * dxB);
            float k1yB = NORM * (shB.z * cB + shB.x * dyB);
            float k1zB = NORM * (shB.w * cB + shB.x * dzB);
            logitA += I3 * (g_qd1[(size_t)dA * 6 + j * 3 + 0] * k1xA +
                            g_qd1[(size_t)dA * 6 + j * 3 + 1] * k1yA +
                            g_qd1[(size_t)dA * 6 + j * 3 + 2] * k1zA);
            logitB += I3 * (g_qd1[(size_t)dB * 6 + j * 3 + 0] * k1xB +
                            g_qd1[(size_t)dB * 6 + j * 3 + 1] * k1yB +
                            g_qd1[(size_t)dB * 6 + j * 3 + 2] * k1zB);
        }
        logitA *= 0.31622776601683794f;  // 1/sqrt(10)
        logitB *= 0.31622776601683794f;
        g_logit[e0] = logitA;
        atomicMaxF(&g_m[dA], logitA);
        if (hb) {
            g_logit[e1] = logitB;
            atomicMaxF(&g_m[dB], logitB);
        }
    }
}

// ---------------------------------------------------------------------------
// L3V kernel (HALF = 0/1, EPT=2): V layer-3 + TP contraction, half outputs
// ---------------------------------------------------------------------------
template <int HALF>
__device__ __forceinline__ int v_wi(int r) {
    if (r < 128) { int a = r >> 3, b = r & 7;        return a * 16 + HALF * 8 + b; }
    if (r < 160) { int t = r - 128; int a = t >> 1;  return 256 + a * 4 + HALF * 2 + (t & 1); }
    if (r < 168) { int t = r - 160; int a = t >> 1;  return 320 + a * 4 + HALF * 2 + (t & 1); }
    { int t = r - 168; int a = t >> 3, b = t & 7;    return 336 + a * 16 + HALF * 8 + b; }
}

template <int HALF>
__global__ void __launch_bounds__(128, 2)
l3v_kernel(const float* __restrict__ edge_sh,
           const int*   __restrict__ eidx,
           const float* __restrict__ fcW3, const float* __restrict__ fcb3,
           int E) {
    extern __shared__ float sm[];
    int tid = threadIdx.x, bs = blockDim.x;
    for (int i = tid; i < 12800; i += bs) {
        int r = i >> 6, c = i & 63;
        sm[i] = fcW3[c * 400 + v_wi<HALF>(r)];
    }
    for (int i = tid; i < 200; i += bs) sm[12800 + i] = fcb3[v_wi<HALF>(i)];
    __syncthreads();
    const float* B3 = sm + 12800;

    const float NORM = 0.22360679774997896f;  // 1/sqrt(20)
    const float I3   = 0.5773502691896258f;   // 1/sqrt(3)

    int stride = gridDim.x * bs;
    for (int e0 = blockIdx.x * bs + tid; e0 < E; e0 += 2 * stride) {
        int e1 = e0 + stride;
        bool hb = e1 < E;
        size_t e1c = hb ? (size_t)e1 : (size_t)e0;

        int sA = eidx[e0], sB = eidx[e1c];
        float4 shA = reinterpret_cast<const float4*>(edge_sh)[e0];
        float4 shB = reinterpret_cast<const float4*>(edge_sh)[e1c];

        ull h2A[32], h2B[32];
        {
            const ulonglong2* ra = reinterpret_cast<const ulonglong2*>(g_h2v + (size_t)e0 * 64);
            const ulonglong2* rb = reinterpret_cast<const ulonglong2*>(g_h2v + e1c * 64);
#pragma unroll
            for (int t = 0; t < 16; t++) {
                ulonglong2 va = ra[t]; ulonglong2 vb = rb[t];
                h2A[2 * t] = va.x; h2A[2 * t + 1] = va.y;
                h2B[2 * t] = vb.x; h2B[2 * t + 1] = vb.y;
            }
        }

        float xl0A[16], xl0B[16], xl1A[12], xl1B[12], ul1A[4], ul1B[4];
#pragma unroll
        for (int o = 0; o < 16; o++) {
            xl0A[o] = g_x0[(size_t)sA * 16 + o];
            xl0B[o] = g_x0[(size_t)sB * 16 + o];
        }
#pragma unroll
        for (int o = 0; o < 12; o++) {
            xl1A[o] = g_x1[(size_t)sA * 12 + o];
            xl1B[o] = g_x1[(size_t)sB * 12 + o];
        }
#pragma unroll
        for (int j = 0; j < 4; j++) {
            ul1A[j] = xl1A[j * 3] * shA.y + xl1A[j * 3 + 1] * shA.z + xl1A[j * 3 + 2] * shA.w;
            ul1B[j] = xl1B[j * 3] * shB.y + xl1B[j * 3 + 1] * shB.z + xl1B[j * 3 + 2] * shB.w;
        }

#pragma unroll 1
        for (int b = 0; b < 8; b++) {
            float a0A = 0.f, a0B = 0.f;
#pragma unroll 2
            for (int a = 0; a < 16; a++) {
                int r = a * 8 + b;
                float wA, wB;
                dotp2<16>(sm + r * 64, h2A, h2B, wA, wB);
                float bb = B3[r];
                a0A = fmaf(xl0A[a], wA + bb, a0A);
                a0B = fmaf(xl0B[a], wB + bb, a0B);
            }
            float a1A = 0.f, a1B = 0.f;
#pragma unroll 2
            for (int a = 0; a < 4; a++) {
                int r = 168 + a * 8 + b;
                float wA, wB;
                dotp2<16>(sm + r * 64, h2A, h2B, wA, wB);
                float bb = B3[r];
                a1A = fmaf(ul1A[a], wA + bb, a1A);
                a1B = fmaf(ul1B[a], wB + bb, a1B);
            }
            int bg = HALF * 8 + b;
            g_v[(size_t)bg * E + e0] = NORM * fmaf(shA.x, a0A, I3 * a1A);
            if (hb) g_v[(size_t)bg * E + e1] = NORM * fmaf(shB.x, a0B, I3 * a1B);
        }
#pragma unroll 1
        for (int j = 0; j < 2; j++) {
            float cA = 0.f, cB = 0.f;
#pragma unroll 2
            for (int a = 0; a < 16; a++) {
                int r = 128 + a * 2 + j;
                float wA, wB;
                dotp2<16>(sm + r * 64, h2A, h2B, wA, wB);
                float bb = B3[r];
                cA = fmaf(xl0A[a], wA + bb, cA);
                cB = fmaf(xl0B[a], wB + bb, cB);
            }
            float dxA = 0.f, dyA = 0.f, dzA = 0.f;
            float dxB = 0.f, dyB = 0.f, dzB = 0.f;
#pragma unroll 2
            for (int a = 0; a < 4; a++) {
                int r = 160 + a * 2 + j;
                float wA, wB;
                dotp2<16>(sm + r * 64, h2A, h2B, wA, wB);
                float bb = B3[r];
                wA += bb; wB += bb;
                dxA = fmaf(xl1A[a * 3 + 0], wA, dxA);
                dyA = fmaf(xl1A[a * 3 + 1], wA, dyA);
                dzA = fmaf(xl1A[a * 3 + 2], wA, dzA);
                dxB = fmaf(xl1B[a * 3 + 0], wB, dxB);
                dyB = fmaf(xl1B[a * 3 + 1], wB, dyB);
                dzB = fmaf(xl1B[a * 3 + 2], wB, dzB);
            }
            int jg = HALF * 2 + j;
            g_v[(size_t)(16 + jg * 3 + 0) * E + e0] = NORM * (shA.y * cA + shA.x * dxA);
            g_v[(size_t)(16 + jg * 3 + 1) * E + e0] = NORM * (shA.z * cA + shA.x * dyA);
            g_v[(size_t)(16 + jg * 3 + 2) * E + e0] = NORM * (shA.w * cA + shA.x * dzA);
            if (hb) {
                g_v[(size_t)(16 + jg * 3 + 0) * E + e1] = NORM * (shB.y * cB + shB.x * dxB);
                g_v[(size_t)(16 + jg * 3 + 1) * E + e1] = NORM * (shB.z * cB + shB.x * dyB);
                g_v[(size_t)(16 + jg * 3 + 2) * E + e1] = NORM * (shB.w * cB + shB.x * dzB);
            }
        }
    }
}

// ---------------------------------------------------------------------------
__global__ void softmax_agg_kernel(const int* __restrict__ eidx, int E) {
    int e = blockIdx.x * blockDim.x + threadIdx.x;
    if (e >= E) return;
    int d = eidx[E + e];
    float p = __expf(g_logit[e] - g_m[d]);
    atomicAdd(&g_z[d], p);
#pragma unroll
    for (int j = 0; j < 28; j++)
        atomicAdd(&g_agg[(size_t)d * 28 + j], p * g_v[(size_t)j * E + e]);
}

// ---------------------------------------------------------------------------
__global__ void node_out_kernel(const float* __restrict__ na,
                                const float* __restrict__ Wo0,
                                const float* __restrict__ Wo1,
                                float* __restrict__ out, int N) {
    __shared__ float sW0[512], sW1[32];
    int tid = threadIdx.x;
    for (int i = tid; i < 512; i += blockDim.x) sW0[i] = Wo0[i];
    for (int i = tid; i < 32;  i += blockDim.x) sW1[i] = Wo1[i];
    __syncthreads();

    int n = blockIdx.x * blockDim.x + tid;
    if (n >= N) return;
    float z = g_z[n];
    float zi = z > 0.f ? 1.f / z : 0.f;
    float ag[28];
#pragma unroll
    for (int j = 0; j < 28; j++) ag[j] = g_agg[(size_t)n * 28 + j] * zi;

#pragma unroll
    for (int o = 0; o < 32; o++) {
        float s = 0.f;
#pragma unroll
        for (int a = 0; a < 16; a++) s = fmaf(ag[a], sW0[a * 32 + o], s);
        out[(size_t)n * 56 + o] = fmaf(s, 0.25f, na[(size_t)n * 56 + o]);
    }
#pragma unroll
    for (int o = 0; o < 8; o++)
#pragma unroll
        for (int c = 0; c < 3; c++) {
            float s = 0.f;
#pragma unroll
            for (int a = 0; a < 4; a++) s = fmaf(ag[16 + a * 3 + c], sW1[a * 8 + o], s);
            out[(size_t)n * 56 + 32 + o * 3 + c] =
                fmaf(s, 0.5f, na[(size_t)n * 56 + 32 + o * 3 + c]);
        }
}

// ---------------------------------------------------------------------------
extern "C" void kernel_launch(void* const* d_in, const int* in_sizes, int n_in,
                              void* d_out, int out_size) {
    const float* node_attr  = (const float*)d_in[0];
    const float* edge_attr  = (const float*)d_in[1];
    const float* edge_sh    = (const float*)d_in[2];
    const int*   edge_index = (const int*)  d_in[3];
    const float* W_in0  = (const float*)d_in[4];
    const float* W_in1  = (const float*)d_in[5];
    const float* Wq0    = (const float*)d_in[6];
    const float* Wq1    = (const float*)d_in[7];
    const float* Wd0    = (const float*)d_in[8];
    const float* Wd1    = (const float*)d_in[9];
    const float* W_out0 = (const float*)d_in[10];
    const float* W_out1 = (const float*)d_in[11];
    const float* fcW1 = (const float*)d_in[12];
    const float* fcb1 = (const float*)d_in[13];
    const float* fcW2 = (const float*)d_in[14];
    const float* fcb2 = (const float*)d_in[15];
    const float* fcW3 = (const float*)d_in[16];
    const float* fcb3 = (const float*)d_in[17];
    const float* fkW1 = (const float*)d_in[18];
    const float* fkb1 = (const float*)d_in[19];
    const float* fkW2 = (const float*)d_in[20];
    const float* fkb2 = (const float*)d_in[21];
    const float* fkW3 = (const float*)d_in[22];
    const float* fkb3 = (const float*)d_in[23];
    float* out = (float*)d_out;

    int N = in_sizes[0] / 56;
    int E = in_sizes[2] / 4;

    const int FRONT_SMEM = F_FLOATS * (int)sizeof(float);   // 50176 B
    const int L3_SMEM    = 13000 * (int)sizeof(float);      // 52000 B

    cudaFuncSetAttribute(front_kernel,
                         cudaFuncAttributeMaxDynamicSharedMemorySize, FRONT_SMEM);
    cudaFuncSetAttribute(l3k_kernel,
                         cudaFuncAttributeMaxDynamicSharedMemorySize, L3_SMEM);
    cudaFuncSetAttribute(l3v_kernel<0>,
                         cudaFuncAttributeMaxDynamicSharedMemorySize, L3_SMEM);
    cudaFuncSetAttribute(l3v_kernel<1>,
                         cudaFuncAttributeMaxDynamicSharedMemorySize, L3_SMEM);

    node_prep_kernel<<<(N + 127) / 128, 128>>>(node_attr, W_in0, W_in1, Wq0, Wq1,
                                               Wd0, Wd1, N);
    init_kernel<<<(N * 28 + 255) / 256, 256>>>(N);
    front_kernel<<<NSM * 2, 128, FRONT_SMEM>>>(edge_attr,
                                               fcW1, fcb1, fcW2, fcb2,
                                               fkW1, fkb1, fkW2, fkb2, E);
    l3k_kernel<<<NSM * 2, 128, L3_SMEM>>>(edge_sh, edge_index, fkW3, fkb3, E);
    l3v_kernel<0><<<NSM * 2, 128, L3_SMEM>>>(edge_sh, edge_index, fcW3, fcb3, E);
    l3v_kernel<1><<<NSM * 2, 128, L3_SMEM>>>(edge_sh, edge_index, fcW3, fcb3, E);
    softmax_agg_kernel<<<(E + 255) / 256, 256>>>(edge_index, E);
    node_out_kernel<<<(N + 127) / 128, 128>>>(node_attr, W_out0, W_out1, out, N);
}